// round 13
// baseline (speedup 1.0000x reference)
#include <cuda_runtime.h>
#include <cstdint>
#include <math.h>

// RZ gate dense matrix, N=12 (confirmed model):
//   output = 16,777,216 float32 (67 MB) = real part of the 4096x4096
//   complex64 matrix; zeros except out[4097*k] = cos(theta/2), k=0..4095.
//   theta = float32 at d_in[0].
//
// R12: TMA-only = 13.7us kernel, ~2600 B/cyc, L2 only 41% -> per-SM TMA store
// rate is the wall, not the L2 port. R9: STG-only ~1340 B/cyc via the LSU
// path. This round: both engines in parallel per CTA (warp 0 = TMA bulk
// stores from one stride-aligned SMEM image; warps 1-7 = STG.128 with the
// diagonal embedded in the store value), 2:1 chunk split, 148 CTAs (1/SM).

static constexpr long long DIM = 4096;
static constexpr int CHUNK_FLOATS = 4 * 4097;          // 16388, stride-aligned
static constexpr int CHUNK_BYTES = CHUNK_FLOATS * 4;   // 65552 (16B multiple)
static constexpr int SMEM_BYTES = CHUNK_BYTES;
static constexpr int BLOCK = 256;                      // 8 warps
static constexpr int GRID = 148;                       // 1 CTA per SM

__device__ __forceinline__ uint32_t smem_u32(const void* p) {
    uint32_t a;
    asm("{ .reg .u64 t; cvta.to.shared.u64 t, %1; cvt.u32.u64 %0, t; }"
        : "=r"(a) : "l"(p));
    return a;
}

__global__ void __launch_bounds__(BLOCK)
rz_hybrid_kernel(const float* __restrict__ theta_p,
                 float* __restrict__ outf,
                 long long nfloats) {
    extern __shared__ __align__(128) float sbuf[];

    int tid = threadIdx.x;
    int wid = tid >> 5;

    float theta = theta_p ? theta_p[0] : 0.f;
    if (!isfinite(theta)) theta = 0.f;
    float cosv = cosf(0.5f * theta);

    // Build the shared SMEM image: zeros + diag at rel 0,4097,8194,12291.
    float4* sb4 = reinterpret_cast<float4*>(sbuf);
    const float4 z = make_float4(0.f, 0.f, 0.f, 0.f);
#pragma unroll
    for (int j = 0; j < 16; ++j)
        sb4[tid + j * BLOCK] = z;
    if (tid == 0) {
        sb4[4096] = z;
        sbuf[0] = cosv;
        sbuf[4097] = cosv;
        sbuf[8194] = cosv;
        sbuf[12291] = cosv;
        asm volatile("fence.proxy.async.shared::cta;" ::: "memory");
    }
    __syncthreads();

    long long nfull = nfloats / CHUNK_FLOATS;           // 1023
    long long tailf = nfloats - nfull * CHUNK_FLOATS;   // 12292
    long long nchunk = nfull + (tailf > 0 ? 1 : 0);     // 1024

    if (wid == 0) {
        // ---- TMA path: chunks with c % 3 != 0 (2/3 of chunks) ----
        if (tid == 0) {
            uint32_t saddr = smem_u32(sbuf);
            for (long long c = blockIdx.x; c < nchunk; c += GRID) {
                if (c % 3 == 0) continue;
                long long cf = (c < nfull) ? CHUNK_FLOATS : tailf;
                unsigned bytes = (unsigned)(cf * 4) & ~15u;
                const float* gdst = outf + c * CHUNK_FLOATS;
                asm volatile(
                    "cp.async.bulk.global.shared::cta.bulk_group [%0], [%1], %2;"
                    :: "l"(gdst), "r"(saddr), "r"(bytes) : "memory");
            }
            asm volatile("cp.async.bulk.commit_group;" ::: "memory");
            asm volatile("cp.async.bulk.wait_group 0;" ::: "memory");
        }
    } else {
        // ---- STG path: chunks with c % 3 == 0 (1/3 of chunks) ----
        int lane = tid - 32;                            // 0..223
        for (long long c = blockIdx.x; c < nchunk; c += GRID) {
            if (c % 3 != 0) continue;
            long long cf = (c < nfull) ? CHUNK_FLOATS : tailf;
            int n4 = (int)(cf >> 2);                    // 4097 or 3073
            float4* g4 = reinterpret_cast<float4*>(outf + c * CHUNK_FLOATS);
            for (int j = lane; j < n4; j += 224) {
                float4 v = z;
                if (j == 0)         v.x = cosv;         // rel 0
                else if (j == 1024) v.y = cosv;         // rel 4097
                else if (j == 2048) v.z = cosv;         // rel 8194
                else if (j == 3072) v.w = cosv;         // rel 12291
                g4[j] = v;
            }
            // leftover floats (cf % 4 != 0): none for real shape
            if (lane == 0) {
                for (long long r = (long long)n4 * 4; r < cf; ++r)
                    outf[c * CHUNK_FLOATS + r] = 0.f;
            }
        }
    }
}

extern "C" void kernel_launch(void* const* d_in, const int* in_sizes, int n_in,
                              void* d_out, int out_size) {
    const float* theta = (n_in >= 1) ? (const float*)d_in[0] : nullptr;
    long long nfloats = (long long)out_size;            // buffer = out_size*4 B

    static bool attr_set = false;
    if (!attr_set) {
        cudaFuncSetAttribute(rz_hybrid_kernel,
                             cudaFuncAttributeMaxDynamicSharedMemorySize,
                             SMEM_BYTES);
        attr_set = true;
    }

    rz_hybrid_kernel<<<GRID, BLOCK, SMEM_BYTES>>>(theta, (float*)d_out,
                                                  nfloats);
}